// round 2
// baseline (speedup 1.0000x reference)
#include <cuda_runtime.h>
#include <math.h>

#define NPTS 120000
#define NCH  128
#define HCH  64
#define TM   64
#define NBLK (NPTS / TM)   // 1875, exact
#define AS_LD 68           // padded A-tile stride (16B-aligned rows, bank-safe)

// Scratch (static device globals — no runtime allocation)
__device__ float g_a[(size_t)NPTS * NCH];
__device__ float g_b[(size_t)NPTS * NCH];
__device__ float g_t[(size_t)NPTS * HCH];
__device__ float g_u[(size_t)NPTS * HCH];

// ---------------------------------------------------------------------------
// Shared-memory staging helpers: 64x64 fp32 tiles, 256 threads, float4 loads
// ---------------------------------------------------------------------------
__device__ __forceinline__ void load_A64(const float* __restrict__ g, int ld,
                                         float* __restrict__ s) {
    int tid = threadIdx.x;
#pragma unroll
    for (int it = 0; it < 4; ++it) {
        int idx = tid + it * 256;        // 0..1023 float4 slots
        int row = idx >> 4;              // 16 float4 per 64-float row
        int c4  = (idx & 15) << 2;
        float4 v = *(const float4*)(g + (size_t)row * ld + c4);
        *(float4*)(s + row * AS_LD + c4) = v;
    }
}

__device__ __forceinline__ void load_W64(const float* __restrict__ g, int ld,
                                         float* __restrict__ s) {
    int tid = threadIdx.x;
#pragma unroll
    for (int it = 0; it < 4; ++it) {
        int idx = tid + it * 256;
        int row = idx >> 4;
        int c4  = (idx & 15) << 2;
        float4 v = *(const float4*)(g + (size_t)row * ld + c4);
        *(float4*)(s + row * 64 + c4) = v;
    }
}

// 64x64x64 fp32 micro-GEMM: acc[4][4] += A_tile @ W_tile
// thread (ty,tx): points ty*4..+4, cols tx*4..+4
__device__ __forceinline__ void mm64(const float* __restrict__ as,
                                     const float* __restrict__ ws,
                                     float acc[4][4], int ty, int tx) {
    const float* ap = as + ty * 4 * AS_LD;
    const float* wp = ws + tx * 4;
#pragma unroll 8
    for (int k = 0; k < 64; ++k) {
        float4 w = *(const float4*)(wp + k * 64);
        float a0 = ap[0 * AS_LD + k];
        float a1 = ap[1 * AS_LD + k];
        float a2 = ap[2 * AS_LD + k];
        float a3 = ap[3 * AS_LD + k];
        acc[0][0] += a0 * w.x; acc[0][1] += a0 * w.y; acc[0][2] += a0 * w.z; acc[0][3] += a0 * w.w;
        acc[1][0] += a1 * w.x; acc[1][1] += a1 * w.y; acc[1][2] += a1 * w.z; acc[1][3] += a1 * w.w;
        acc[2][0] += a2 * w.x; acc[2][1] += a2 * w.y; acc[2][2] += a2 * w.z; acc[2][3] += a2 * w.w;
        acc[3][0] += a3 * w.x; acc[3][1] += a3 * w.y; acc[3][2] += a3 * w.z; acc[3][3] += a3 * w.w;
    }
}

// ---------------------------------------------------------------------------
// fc1: g_t = relu(in @ W1), in: [NPTS,128] (x / g_a / g_b), W1: [128,64]
// ---------------------------------------------------------------------------
__global__ void __launch_bounds__(256)
fc1_kernel(const float* __restrict__ x, int insel, const float* __restrict__ W1) {
    __shared__ float as[TM * AS_LD];
    __shared__ float ws[64 * 64];
    const float* in = (insel == 0) ? x : (insel == 1 ? g_a : g_b);

    int p0 = blockIdx.x * TM;
    int tid = threadIdx.x, tx = tid & 15, ty = tid >> 4;
    float acc[4][4] = {};

#pragma unroll
    for (int ck = 0; ck < 2; ++ck) {
        load_A64(in + (size_t)p0 * NCH + ck * 64, NCH, as);
        load_W64(W1 + (size_t)ck * 64 * HCH, HCH, ws);
        __syncthreads();
        mm64(as, ws, acc, ty, tx);
        __syncthreads();
    }

#pragma unroll
    for (int i = 0; i < 4; ++i) {
        int p = p0 + ty * 4 + i;
        float4 v = make_float4(fmaxf(acc[i][0], 0.f), fmaxf(acc[i][1], 0.f),
                               fmaxf(acc[i][2], 0.f), fmaxf(acc[i][3], 0.f));
        *(float4*)(g_t + (size_t)p * HCH + tx * 4) = v;
    }
}

// ---------------------------------------------------------------------------
// conv3: g_u = relu( sum_{kk=0..26} gather(g_t, nbr[:,kk]) @ Wk[kk] )
// ---------------------------------------------------------------------------
__global__ void __launch_bounds__(256)
conv_kernel(const float* __restrict__ Wk, const int* __restrict__ nbr) {
    __shared__ float gs[TM * AS_LD];
    __shared__ float ws[64 * 64];

    int p0 = blockIdx.x * TM;
    int tid = threadIdx.x, tx = tid & 15, ty = tid >> 4;
    int lp = tid >> 2;               // point within tile (4 threads per point)
    int c0 = (tid & 3) * 16;         // 16 floats per thread
    float acc[4][4] = {};

    for (int kk = 0; kk < 27; ++kk) {
        load_W64(Wk + (size_t)kk * 64 * 64, 64, ws);
        int nb = nbr[(size_t)(p0 + lp) * 27 + kk];
        const float* src = g_t + (size_t)(nb < 0 ? 0 : nb) * HCH;
#pragma unroll
        for (int c = 0; c < 16; c += 4) {
            float4 v = make_float4(0.f, 0.f, 0.f, 0.f);
            if (nb >= 0) v = *(const float4*)(src + c0 + c);
            *(float4*)(gs + lp * AS_LD + c0 + c) = v;
        }
        __syncthreads();
        mm64(gs, ws, acc, ty, tx);
        __syncthreads();
    }

#pragma unroll
    for (int i = 0; i < 4; ++i) {
        int p = p0 + ty * 4 + i;
        float4 v = make_float4(fmaxf(acc[i][0], 0.f), fmaxf(acc[i][1], 0.f),
                               fmaxf(acc[i][2], 0.f), fmaxf(acc[i][3], 0.f));
        *(float4*)(g_u + (size_t)p * HCH + tx * 4) = v;
    }
}

// ---------------------------------------------------------------------------
// fc2: out = relu(g_u @ W2 + h); W2: [64,128]; grid.y = 2 column tiles
//      h/out selected: 0 -> x (read-only h only), 1 -> g_a, 2 -> g_b
// ---------------------------------------------------------------------------
__global__ void __launch_bounds__(256)
fc2_kernel(const float* __restrict__ x, const float* __restrict__ W2,
           int hsel, int outsel) {
    __shared__ float as[TM * AS_LD];
    __shared__ float ws[64 * 64];
    const float* h   = (hsel == 0) ? x : (hsel == 1 ? g_a : g_b);
    float*       out = (outsel == 1) ? g_a : g_b;

    int p0 = blockIdx.x * TM;
    int cb = blockIdx.y * 64;
    int tid = threadIdx.x, tx = tid & 15, ty = tid >> 4;
    float acc[4][4] = {};

    load_A64(g_u + (size_t)p0 * HCH, HCH, as);
    load_W64(W2 + cb, NCH, ws);
    __syncthreads();
    mm64(as, ws, acc, ty, tx);

#pragma unroll
    for (int i = 0; i < 4; ++i) {
        int p = p0 + ty * 4 + i;
        const float4 hv = *(const float4*)(h + (size_t)p * NCH + cb + tx * 4);
        float4 v = make_float4(fmaxf(acc[i][0] + hv.x, 0.f),
                               fmaxf(acc[i][1] + hv.y, 0.f),
                               fmaxf(acc[i][2] + hv.z, 0.f),
                               fmaxf(acc[i][3] + hv.w, 0.f));
        *(float4*)(out + (size_t)p * NCH + cb + tx * 4) = v;
    }
}

// ---------------------------------------------------------------------------
// final: out = g_a * sigmoid(g_b @ Wf) + x ; Wf: [128,128]; grid.y = 2
// ---------------------------------------------------------------------------
__global__ void __launch_bounds__(256)
final_kernel(const float* __restrict__ x, const float* __restrict__ Wf,
             float* __restrict__ out) {
    __shared__ float as[TM * AS_LD];
    __shared__ float ws[64 * 64];

    int p0 = blockIdx.x * TM;
    int cb = blockIdx.y * 64;
    int tid = threadIdx.x, tx = tid & 15, ty = tid >> 4;
    float acc[4][4] = {};

#pragma unroll
    for (int ck = 0; ck < 2; ++ck) {
        load_A64(g_b + (size_t)p0 * NCH + ck * 64, NCH, as);
        load_W64(Wf + (size_t)(ck * 64) * NCH + cb, NCH, ws);
        __syncthreads();
        mm64(as, ws, acc, ty, tx);
        __syncthreads();
    }

#pragma unroll
    for (int i = 0; i < 4; ++i) {
        int p = p0 + ty * 4 + i;
        size_t idx = (size_t)p * NCH + cb + tx * 4;
        const float4 av = *(const float4*)(g_a + idx);
        const float4 xv = *(const float4*)(x + idx);
        float4 v;
        v.x = av.x * (1.f / (1.f + expf(-acc[i][0]))) + xv.x;
        v.y = av.y * (1.f / (1.f + expf(-acc[i][1]))) + xv.y;
        v.z = av.z * (1.f / (1.f + expf(-acc[i][2]))) + xv.z;
        v.w = av.w * (1.f / (1.f + expf(-acc[i][3]))) + xv.w;
        *(float4*)(out + idx) = v;
    }
}

// ---------------------------------------------------------------------------
// Launch: 2 branches x 3 residual units, then gated merge
// Inputs (metadata order): x, W1s(6,128,64), Wks(6,27,64,64), W2s(6,64,128),
//                          Wf(128,128), nbr_idx(NPTS,27) int32
// ---------------------------------------------------------------------------
extern "C" void kernel_launch(void* const* d_in, const int* in_sizes, int n_in,
                              void* d_out, int out_size) {
    const float* x   = (const float*)d_in[0];
    const float* W1s = (const float*)d_in[1];
    const float* Wks = (const float*)d_in[2];
    const float* W2s = (const float*)d_in[3];
    const float* Wf  = (const float*)d_in[4];
    const int*   nbr = (const int*)d_in[5];
    float*       out = (float*)d_out;

    dim3 g1(NBLK), g2(NBLK, 2), blk(256);

    // branch a (units 0..2), accumulator g_a (sel 1)
    for (int i = 0; i < 3; ++i) {
        int hsel = (i == 0) ? 0 : 1;
        fc1_kernel<<<g1, blk>>>(x, hsel, W1s + (size_t)i * NCH * HCH);
        conv_kernel<<<g1, blk>>>(Wks + (size_t)i * 27 * HCH * HCH, nbr);
        fc2_kernel<<<g2, blk>>>(x, W2s + (size_t)i * HCH * NCH, hsel, 1);
    }
    // branch b (units 3..5), accumulator g_b (sel 2)
    for (int i = 3; i < 6; ++i) {
        int hsel = (i == 3) ? 0 : 2;
        fc1_kernel<<<g1, blk>>>(x, hsel, W1s + (size_t)i * NCH * HCH);
        conv_kernel<<<g1, blk>>>(Wks + (size_t)i * 27 * HCH * HCH, nbr);
        fc2_kernel<<<g2, blk>>>(x, W2s + (size_t)i * HCH * NCH, hsel, 2);
    }
    final_kernel<<<g2, blk>>>(x, Wf, out);
}

// round 4
// speedup vs baseline: 2.2604x; 2.2604x over previous
#include <cuda_runtime.h>
#include <cuda_bf16.h>
#include <cstdint>
#include <math.h>

#define NPTS 120000
#define NBLK 938   // ceil(120000/128)

// ------------------------- static device scratch ---------------------------
__device__ float g_a[(size_t)NPTS * 128];
__device__ float g_b[(size_t)NPTS * 128];
__device__ __nv_bfloat16 g_t_hi[(size_t)NPTS * 64];
__device__ __nv_bfloat16 g_t_lo[(size_t)NPTS * 64];
__device__ __nv_bfloat16 g_u_hi[(size_t)NPTS * 64];
__device__ __nv_bfloat16 g_u_lo[(size_t)NPTS * 64];

// preconverted weights, transposed to [n][k], split bf16 hi/lo
__device__ __nv_bfloat16 w1t_hi[49152],  w1t_lo[49152];    // 6 x [64n][128k]
__device__ __nv_bfloat16 wkt_hi[663552], wkt_lo[663552];   // 6 x 27 x [64n][64k]
__device__ __nv_bfloat16 w2t_hi[49152],  w2t_lo[49152];    // 6 x [128n][64k]
__device__ __nv_bfloat16 wft_hi[16384],  wft_lo[16384];    // [128n][128k]

// ------------------------------ helpers ------------------------------------
__device__ __forceinline__ uint32_t smem_u32(const void* p) {
    uint32_t a;
    asm("{ .reg .u64 t; cvta.to.shared.u64 t, %1; cvt.u32.u64 %0, t; }" : "=r"(a) : "l"(p));
    return a;
}
__device__ __forceinline__ uint32_t sw128(uint32_t off) { return off ^ ((off >> 3) & 0x70); }

__device__ __forceinline__ uint32_t packbf(float x, float y) {  // low=bf16(x), high=bf16(y)
    uint32_t r;
    asm("cvt.rn.bf16x2.f32 %0, %1, %2;" : "=r"(r) : "f"(y), "f"(x));
    return r;
}
__device__ __forceinline__ float lo2f(uint32_t p) { return __uint_as_float(p << 16); }
__device__ __forceinline__ float hi2f(uint32_t p) { return __uint_as_float(p & 0xFFFF0000u); }

__device__ __forceinline__ void sts64(uint32_t a, uint32_t x, uint32_t y) {
    asm volatile("st.shared.v2.b32 [%0], {%1,%2};" :: "r"(a), "r"(x), "r"(y) : "memory");
}
__device__ __forceinline__ void cpasync16(uint32_t dst, const void* src, uint32_t zf) {
    asm volatile("cp.async.cg.shared.global [%0], [%1], 16, %2;"
                 :: "r"(dst), "l"(src), "r"(zf) : "memory");
}
#define CP_COMMIT() asm volatile("cp.async.commit_group;" ::: "memory")
#define CP_WAIT(n)  asm volatile("cp.async.wait_group %0;" :: "n"(n) : "memory")

__device__ __forceinline__ void ldm4(uint32_t r[4], uint32_t addr) {
    asm volatile("ldmatrix.sync.aligned.m8n8.x4.shared.b16 {%0,%1,%2,%3}, [%4];"
                 : "=r"(r[0]), "=r"(r[1]), "=r"(r[2]), "=r"(r[3]) : "r"(addr));
}
__device__ __forceinline__ void mma16816(float d[4], const uint32_t a[4],
                                         uint32_t b0, uint32_t b1) {
    asm volatile("mma.sync.aligned.m16n8k16.row.col.f32.bf16.bf16.f32 "
                 "{%0,%1,%2,%3}, {%4,%5,%6,%7}, {%8,%9}, {%0,%1,%2,%3};"
                 : "+f"(d[0]), "+f"(d[1]), "+f"(d[2]), "+f"(d[3])
                 : "r"(a[0]), "r"(a[1]), "r"(a[2]), "r"(a[3]), "r"(b0), "r"(b1));
}

// --------------------- K=64 chunk: split-bf16 3-pass MMA --------------------
// A tile: [128m][64k] bf16 SW128 (hi at Ah, lo at Al), B tile: [64n][64k] (Bh,Bl)
// warp (m0 = (wid&3)*32, n0w = (wid>>2)*32) accumulates m32 x n32 into acc.
__device__ __forceinline__ void mma_chunk(float acc[2][4][4],
                                          uint32_t Ah, uint32_t Al,
                                          uint32_t Bh, uint32_t Bl,
                                          int m0, int n0w, int lane) {
    const int ar = lane & 15, ak = (lane >> 4) << 3;
    const int bn = (lane & 7) + ((lane & 16) ? 8 : 0), bk = ((lane >> 3) & 1) << 3;
#pragma unroll
    for (int ks = 0; ks < 4; ++ks) {
        uint32_t ah[2][4], al[2][4], bh[2][4], bl[2][4];
#pragma unroll
        for (int mt = 0; mt < 2; ++mt) {
            uint32_t off = sw128((uint32_t)((m0 + mt * 16 + ar) * 128 + (ks * 16 + ak) * 2));
            ldm4(ah[mt], Ah + off);
            ldm4(al[mt], Al + off);
        }
#pragma unroll
        for (int g = 0; g < 2; ++g) {
            uint32_t off = sw128((uint32_t)((n0w + g * 16 + bn) * 128 + (ks * 16 + bk) * 2));
            ldm4(bh[g], Bh + off);
            ldm4(bl[g], Bl + off);
        }
#pragma unroll
        for (int mt = 0; mt < 2; ++mt)
#pragma unroll
            for (int nt = 0; nt < 4; ++nt) {
                int g = nt >> 1, o = (nt & 1) << 1;
                mma16816(acc[mt][nt], ah[mt], bh[g][o], bh[g][o + 1]);
                mma16816(acc[mt][nt], ah[mt], bl[g][o], bl[g][o + 1]);
                mma16816(acc[mt][nt], al[mt], bh[g][o], bh[g][o + 1]);
            }
    }
}

// --------------------------- staging helpers -------------------------------
// A copy-stage from bf16 planes (row index nb, -1 => zero-fill). 1 row-plane/thread.
__device__ __forceinline__ void stageA_copy(uint32_t Sa, const __nv_bfloat16* hi,
                                            const __nv_bfloat16* lo, int nb, int tid) {
    int row = tid >> 1, plane = tid & 1;
    const __nv_bfloat16* src = (plane ? lo : hi) + (size_t)(nb < 0 ? 0 : nb) * 64;
    uint32_t zf = (nb >= 0) ? 16u : 0u;
    uint32_t base = Sa + (plane << 14);
#pragma unroll
    for (int j = 0; j < 8; ++j)
        cpasync16(base + sw128((uint32_t)(row * 128 + j * 16)),
                  (const char*)src + j * 16, zf);
}

// B copy-stage: 64 rows of 128B from [n][srcld] bf16 planes at column koff
__device__ __forceinline__ void stageB_rows(uint32_t Sb, const __nv_bfloat16* hi,
                                            const __nv_bfloat16* lo, int srcld,
                                            int koff, int tid) {
#pragma unroll
    for (int j = 0; j < 4; ++j) {
        int fl = tid + (j << 8);
        int plane = fl >> 9;
        int r9 = fl & 511;
        int n = r9 >> 3, jj = r9 & 7;
        const __nv_bfloat16* src = (plane ? lo : hi) + (size_t)n * srcld + koff + jj * 8;
        cpasync16(Sb + (plane << 13) + sw128((uint32_t)(n * 128 + jj * 16)), src, 16u);
    }
}

// A convert-stage from fp32 [p][ld], split into hi/lo planes in smem (STS path)
__device__ __forceinline__ void stageA_cvt(uint32_t Sa, const float* __restrict__ A,
                                           int ld, int koff, int p0, int tid) {
    int row = tid >> 1, half = tid & 1, p = p0 + row;
    const float* src = A + (size_t)p * ld + koff + half * 32;
#pragma unroll
    for (int j = 0; j < 8; ++j) {
        float4 v = make_float4(0.f, 0.f, 0.f, 0.f);
        if (p < NPTS) v = *(const float4*)(src + j * 4);
        uint32_t h01 = packbf(v.x, v.y), h23 = packbf(v.z, v.w);
        uint32_t l01 = packbf(v.x - lo2f(h01), v.y - hi2f(h01));
        uint32_t l23 = packbf(v.z - lo2f(h23), v.w - hi2f(h23));
        uint32_t off = sw128((uint32_t)(row * 128 + (half * 32 + j * 4) * 2));
        sts64(Sa + off, h01, h23);
        sts64(Sa + 16384 + off, l01, l23);
    }
}

// relu + bf16-split epilogue into activation planes (cols 0..63)
__device__ __forceinline__ void epi_planes(const float acc[2][4][4],
                                           __nv_bfloat16* ghi, __nv_bfloat16* glo,
                                           int p0, int m0, int n0w, int lane) {
    int r0 = lane >> 2, c0 = (lane & 3) << 1;
#pragma unroll
    for (int mt = 0; mt < 2; ++mt)
#pragma unroll
        for (int nt = 0; nt < 4; ++nt)
#pragma unroll
            for (int h = 0; h < 2; ++h) {
                int p = p0 + m0 + mt * 16 + r0 + h * 8;
                if (p >= NPTS) continue;
                int col = n0w + nt * 8 + c0;
                float v0 = fmaxf(acc[mt][nt][h * 2 + 0], 0.f);
                float v1 = fmaxf(acc[mt][nt][h * 2 + 1], 0.f);
                uint32_t hi = packbf(v0, v1);
                uint32_t lo = packbf(v0 - lo2f(hi), v1 - hi2f(hi));
                *(uint32_t*)(ghi + (size_t)p * 64 + col) = hi;
                *(uint32_t*)(glo + (size_t)p * 64 + col) = lo;
            }
}

extern __shared__ char dsm[];

// ------------------------- weight prep (once per graph) --------------------
__global__ void prep_kernel(const float* __restrict__ W1s, const float* __restrict__ Wks,
                            const float* __restrict__ W2s, const float* __restrict__ Wf) {
    int idx = blockIdx.x * 256 + threadIdx.x;
    float w;
    __nv_bfloat16 *dh, *dl;
    size_t d;
    if (idx < 49152) {
        int i = idx / 8192, r = idx % 8192, n = r / 128, k = r % 128;
        w = W1s[(size_t)i * 8192 + (size_t)k * 64 + n];
        dh = w1t_hi; dl = w1t_lo; d = (size_t)i * 8192 + n * 128 + k;
    } else if (idx < 712704) {
        int t = idx - 49152;
        int j = t / 4096, r = t % 4096, n = r / 64, k = r % 64;
        w = Wks[(size_t)j * 4096 + (size_t)k * 64 + n];
        dh = wkt_hi; dl = wkt_lo; d = (size_t)j * 4096 + n * 64 + k;
    } else if (idx < 761856) {
        int t = idx - 712704;
        int i = t / 8192, r = t % 8192, n = r / 64, k = r % 64;
        w = W2s[(size_t)i * 8192 + (size_t)k * 128 + n];
        dh = w2t_hi; dl = w2t_lo; d = (size_t)i * 8192 + n * 64 + k;
    } else if (idx < 778240) {
        int t = idx - 761856;
        int n = t / 128, k = t % 128;
        w = Wf[(size_t)k * 128 + n];
        dh = wft_hi; dl = wft_lo; d = (size_t)n * 128 + k;
    } else return;
    __nv_bfloat16 h = __float2bfloat16(w);
    dh[d] = h;
    dl[d] = __float2bfloat16(w - __bfloat162float(h));
}

// --------------------------------- conv ------------------------------------
// g_u(planes) = relu( sum_kk gather(g_t planes, nbr[:,kk]) @ Wk[kk] )
// double-buffered cp.async stages; acc in registers across all 27 taps.
__global__ void __launch_bounds__(256)
conv_kernel(const int* __restrict__ nbr, int layer) {
    uint32_t sb = smem_u32(dsm);
    int tid = threadIdx.x, lane = tid & 31, wid = tid >> 5;
    int p0 = blockIdx.x * 128;
    int m0 = (wid & 3) * 32, n0w = (wid >> 2) * 32;
    const __nv_bfloat16* wh = wkt_hi + (size_t)layer * 27 * 4096;
    const __nv_bfloat16* wl = wkt_lo + (size_t)layer * 27 * 4096;
    int prow = p0 + (tid >> 1);
    float acc[2][4][4] = {};

    {   // prologue: stage kk=0 into buffer 0
        int nb = (prow < NPTS) ? nbr[(size_t)prow * 27] : -1;
        stageA_copy(sb, g_t_hi, g_t_lo, nb, tid);
        stageB_rows(sb + 32768, wh, wl, 64, 0, tid);
        CP_COMMIT();
    }
    for (int kk = 0; kk < 27; ++kk) {
        uint32_t S = sb + (uint32_t)(kk & 1) * 49152;
        if (kk < 26) {
            uint32_t S2 = sb + (uint32_t)((kk + 1) & 1) * 49152;
            int nb = (prow < NPTS) ? nbr[(size_t)prow * 27 + kk + 1] : -1;
            stageA_copy(S2, g_t_hi, g_t_lo, nb, tid);
            stageB_rows(S2 + 32768, wh + (size_t)(kk + 1) * 4096,
                        wl + (size_t)(kk + 1) * 4096, 64, 0, tid);
            CP_COMMIT();
            CP_WAIT(1);
        } else {
            CP_WAIT(0);
        }
        __syncthreads();
        mma_chunk(acc, S, S + 16384, S + 32768, S + 40960, m0, n0w, lane);
        __syncthreads();
    }
    epi_planes(acc, g_u_hi, g_u_lo, p0, m0, n0w, lane);
}

// ------------------------------ fc1 ----------------------------------------
// g_t(planes) = relu( sel(x,g_a,g_b) @ W1[layer] ), K=128 (2 chunks), N=64
__global__ void __launch_bounds__(256)
fc1_kernel(const float* __restrict__ x, int asel, int layer) {
    uint32_t sb = smem_u32(dsm);
    int tid = threadIdx.x, lane = tid & 31, wid = tid >> 5;
    int p0 = blockIdx.x * 128;
    int m0 = (wid & 3) * 32, n0w = (wid >> 2) * 32;
    const float* A = (asel == 0) ? x : (asel == 1) ? g_a : g_b;
    const __nv_bfloat16* wh = w1t_hi + (size_t)layer * 8192;
    const __nv_bfloat16* wl = w1t_lo + (size_t)layer * 8192;
    float acc[2][4][4] = {};

#pragma unroll
    for (int ck = 0; ck < 2; ++ck) {
        stageA_cvt(sb, A, 128, ck * 64, p0, tid);
        stageB_rows(sb + 32768, wh, wl, 128, ck * 64, tid);
        CP_COMMIT();
        CP_WAIT(0);
        __syncthreads();
        mma_chunk(acc, sb, sb + 16384, sb + 32768, sb + 40960, m0, n0w, lane);
        __syncthreads();
    }
    epi_planes(acc, g_t_hi, g_t_lo, p0, m0, n0w, lane);
}

// ------------------------------ fc2 ----------------------------------------
// out(fp32) = relu( g_u(planes) @ W2[layer] + res ), N=128 via blockIdx.y
__global__ void __launch_bounds__(256)
fc2_kernel(const float* __restrict__ x, int layer, int rsel, int osel) {
    uint32_t sb = smem_u32(dsm);
    int tid = threadIdx.x, lane = tid & 31, wid = tid >> 5;
    int p0 = blockIdx.x * 128, cb = blockIdx.y * 64;
    int m0 = (wid & 3) * 32, n0w = (wid >> 2) * 32;
    const float* res = (rsel == 0) ? x : (rsel == 1) ? g_a : g_b;
    float* out = (osel == 1) ? g_a : g_b;
    const __nv_bfloat16* wh = w2t_hi + (size_t)layer * 8192 + (size_t)cb * 64;
    const __nv_bfloat16* wl = w2t_lo + (size_t)layer * 8192 + (size_t)cb * 64;
    float acc[2][4][4] = {};

    int prow = p0 + (tid >> 1);
    stageA_copy(sb, g_u_hi, g_u_lo, (prow < NPTS) ? prow : -1, tid);
    stageB_rows(sb + 32768, wh, wl, 64, 0, tid);
    CP_COMMIT();
    CP_WAIT(0);
    __syncthreads();
    mma_chunk(acc, sb, sb + 16384, sb + 32768, sb + 40960, m0, n0w, lane);

    int r0 = lane >> 2, c0 = (lane & 3) << 1;
#pragma unroll
    for (int mt = 0; mt < 2; ++mt)
#pragma unroll
        for (int nt = 0; nt < 4; ++nt)
#pragma unroll
            for (int h = 0; h < 2; ++h) {
                int p = p0 + m0 + mt * 16 + r0 + h * 8;
                if (p >= NPTS) continue;
                int col = cb + n0w + nt * 8 + c0;
                float2 rv = *(const float2*)(res + (size_t)p * 128 + col);
                float2 v;
                v.x = fmaxf(acc[mt][nt][h * 2 + 0] + rv.x, 0.f);
                v.y = fmaxf(acc[mt][nt][h * 2 + 1] + rv.y, 0.f);
                *(float2*)(out + (size_t)p * 128 + col) = v;
            }
}

// ------------------------------ final --------------------------------------
// out = g_a * sigmoid(g_b @ Wf) + x,  K=128 (2 chunks), N=128 via blockIdx.y
__global__ void __launch_bounds__(256)
final_kernel(const float* __restrict__ x, float* __restrict__ out) {
    uint32_t sb = smem_u32(dsm);
    int tid = threadIdx.x, lane = tid & 31, wid = tid >> 5;
    int p0 = blockIdx.x * 128, cb = blockIdx.y * 64;
    int m0 = (wid & 3) * 32, n0w = (wid >> 2) * 32;
    const __nv_bfloat16* wh = wft_hi + (size_t)cb * 128;
    const __nv_bfloat16* wl = wft_lo + (size_t)cb * 128;
    float acc[2][4][4] = {};

#pragma unroll
    for (int ck = 0; ck < 2; ++ck) {
        stageA_cvt(sb, g_b, 128, ck * 64, p0, tid);
        stageB_rows(sb + 32768, wh, wl, 128, ck * 64, tid);
        CP_COMMIT();
        CP_WAIT(0);
        __syncthreads();
        mma_chunk(acc, sb, sb + 16384, sb + 32768, sb + 40960, m0, n0w, lane);
        __syncthreads();
    }

    int r0 = lane >> 2, c0 = (lane & 3) << 1;
#pragma unroll
    for (int mt = 0; mt < 2; ++mt)
#pragma unroll
        for (int nt = 0; nt < 4; ++nt)
#pragma unroll
            for (int h = 0; h < 2; ++h) {
                int p = p0 + m0 + mt * 16 + r0 + h * 8;
                if (p >= NPTS) continue;
                int col = cb + n0w + nt * 8 + c0;
                float2 av = *(const float2*)(g_a + (size_t)p * 128 + col);
                float2 xv = *(const float2*)(x + (size_t)p * 128 + col);
                float t0 = acc[mt][nt][h * 2 + 0], t1 = acc[mt][nt][h * 2 + 1];
                float2 v;
                v.x = av.x * (1.f / (1.f + __expf(-t0))) + xv.x;
                v.y = av.y * (1.f / (1.f + __expf(-t1))) + xv.y;
                *(float2*)(out + (size_t)p * 128 + col) = v;
            }
}

// ---------------------------------------------------------------------------
extern "C" void kernel_launch(void* const* d_in, const int* in_sizes, int n_in,
                              void* d_out, int out_size) {
    const float* x   = (const float*)d_in[0];
    const float* W1s = (const float*)d_in[1];
    const float* Wks = (const float*)d_in[2];
    const float* W2s = (const float*)d_in[3];
    const float* Wf  = (const float*)d_in[4];
    const int*   nbr = (const int*)d_in[5];
    float*       out = (float*)d_out;

    cudaFuncSetAttribute(conv_kernel,  cudaFuncAttributeMaxDynamicSharedMemorySize, 98304);
    cudaFuncSetAttribute(fc1_kernel,   cudaFuncAttributeMaxDynamicSharedMemorySize, 49152);
    cudaFuncSetAttribute(fc2_kernel,   cudaFuncAttributeMaxDynamicSharedMemorySize, 49152);
    cudaFuncSetAttribute(final_kernel, cudaFuncAttributeMaxDynamicSharedMemorySize, 49152);

    dim3 blk(256), g1(NBLK), g2(NBLK, 2);

    prep_kernel<<<3040, 256>>>(W1s, Wks, W2s, Wf);

    for (int i = 0; i < 6; ++i) {
        int branch = (i < 3) ? 1 : 2;
        int hsel   = (i == 0 || i == 3) ? 0 : branch;
        fc1_kernel<<<g1, blk, 49152>>>(x, hsel, i);
        conv_kernel<<<g1, blk, 98304>>>(nbr, i);
        fc2_kernel<<<g2, blk, 49152>>>(x, i, hsel, branch);
    }
    final_kernel<<<g2, blk, 49152>>>(x, out);
}

// round 5
// speedup vs baseline: 2.6746x; 1.1833x over previous
#include <cuda_runtime.h>
#include <cuda_bf16.h>
#include <cstdint>
#include <math.h>

#define NPTS 120000
#define NBLK 938   // ceil(120000/128)

// ------------------------- static device scratch ---------------------------
// all activations live as split-bf16 hi/lo planes
__device__ __nv_bfloat16 xp_hi[(size_t)NPTS * 128], xp_lo[(size_t)NPTS * 128];
__device__ __nv_bfloat16 ab_hi[2][(size_t)NPTS * 128], ab_lo[2][(size_t)NPTS * 128];
__device__ __nv_bfloat16 t_hi[2][(size_t)NPTS * 64],  t_lo[2][(size_t)NPTS * 64];
__device__ __nv_bfloat16 u_hi[2][(size_t)NPTS * 64],  u_lo[2][(size_t)NPTS * 64];

// preconverted weights, transposed to [n][k], split bf16 hi/lo
__device__ __nv_bfloat16 w1t_hi[49152],  w1t_lo[49152];    // 6 x [64n][128k]
__device__ __nv_bfloat16 wkt_hi[663552], wkt_lo[663552];   // 6 x 27 x [64n][64k]
__device__ __nv_bfloat16 w2t_hi[49152],  w2t_lo[49152];    // 6 x [128n][64k]
__device__ __nv_bfloat16 wft_hi[16384],  wft_lo[16384];    // [128n][128k]

// ------------------------------ helpers ------------------------------------
__device__ __forceinline__ uint32_t smem_u32(const void* p) {
    uint32_t a;
    asm("{ .reg .u64 t; cvta.to.shared.u64 t, %1; cvt.u32.u64 %0, t; }" : "=r"(a) : "l"(p));
    return a;
}
__device__ __forceinline__ uint32_t sw128(uint32_t off) { return off ^ ((off >> 3) & 0x70); }

__device__ __forceinline__ uint32_t packbf(float x, float y) {  // low=bf16(x), high=bf16(y)
    uint32_t r;
    asm("cvt.rn.bf16x2.f32 %0, %1, %2;" : "=r"(r) : "f"(y), "f"(x));
    return r;
}
__device__ __forceinline__ float lo2f(uint32_t p) { return __uint_as_float(p << 16); }
__device__ __forceinline__ float hi2f(uint32_t p) { return __uint_as_float(p & 0xFFFF0000u); }

__device__ __forceinline__ void cpasync16(uint32_t dst, const void* src, uint32_t zf) {
    asm volatile("cp.async.cg.shared.global [%0], [%1], 16, %2;"
                 :: "r"(dst), "l"(src), "r"(zf) : "memory");
}
#define CP_COMMIT() asm volatile("cp.async.commit_group;" ::: "memory")
#define CP_WAIT(n)  asm volatile("cp.async.wait_group %0;" :: "n"(n) : "memory")

__device__ __forceinline__ void ldm4(uint32_t r[4], uint32_t addr) {
    asm volatile("ldmatrix.sync.aligned.m8n8.x4.shared.b16 {%0,%1,%2,%3}, [%4];"
                 : "=r"(r[0]), "=r"(r[1]), "=r"(r[2]), "=r"(r[3]) : "r"(addr));
}
__device__ __forceinline__ void mma16816(float d[4], const uint32_t a[4],
                                         uint32_t b0, uint32_t b1) {
    asm volatile("mma.sync.aligned.m16n8k16.row.col.f32.bf16.bf16.f32 "
                 "{%0,%1,%2,%3}, {%4,%5,%6,%7}, {%8,%9}, {%0,%1,%2,%3};"
                 : "+f"(d[0]), "+f"(d[1]), "+f"(d[2]), "+f"(d[3])
                 : "r"(a[0]), "r"(a[1]), "r"(a[2]), "r"(a[3]), "r"(b0), "r"(b1));
}

// ---------------- K=64 chunk MMA, 8-warp variant (m32 x n32 / warp) ---------
__device__ __forceinline__ void mma_chunk32(float acc[2][4][4],
                                            uint32_t Ah, uint32_t Al,
                                            uint32_t Bh, uint32_t Bl,
                                            int m0, int n0w, int lane) {
    const int ar = lane & 15, ak = (lane >> 4) << 3;
    const int bn = (lane & 7) + ((lane & 16) ? 8 : 0), bk = ((lane >> 3) & 1) << 3;
#pragma unroll
    for (int ks = 0; ks < 4; ++ks) {
        uint32_t ah[2][4], al[2][4], bh[2][4], bl[2][4];
#pragma unroll
        for (int mt = 0; mt < 2; ++mt) {
            uint32_t off = sw128((uint32_t)((m0 + mt * 16 + ar) * 128 + (ks * 16 + ak) * 2));
            ldm4(ah[mt], Ah + off);
            ldm4(al[mt], Al + off);
        }
#pragma unroll
        for (int g = 0; g < 2; ++g) {
            uint32_t off = sw128((uint32_t)((n0w + g * 16 + bn) * 128 + (ks * 16 + bk) * 2));
            ldm4(bh[g], Bh + off);
            ldm4(bl[g], Bl + off);
        }
#pragma unroll
        for (int mt = 0; mt < 2; ++mt)
#pragma unroll
            for (int nt = 0; nt < 4; ++nt) {
                int g = nt >> 1, o = (nt & 1) << 1;
                mma16816(acc[mt][nt], ah[mt], bh[g][o], bh[g][o + 1]);
                mma16816(acc[mt][nt], ah[mt], bl[g][o], bl[g][o + 1]);
                mma16816(acc[mt][nt], al[mt], bh[g][o], bh[g][o + 1]);
            }
    }
}

// ---------------- K=64 chunk MMA, 16-warp variant (m32 x n16 / warp) --------
__device__ __forceinline__ void mma_chunk16(float acc[2][2][4],
                                            uint32_t Ah, uint32_t Al,
                                            uint32_t Bh, uint32_t Bl,
                                            int m0, int n0w, int lane) {
    const int ar = lane & 15, ak = (lane >> 4) << 3;
    const int bn = (lane & 7) + ((lane & 16) ? 8 : 0), bk = ((lane >> 3) & 1) << 3;
#pragma unroll
    for (int ks = 0; ks < 4; ++ks) {
        uint32_t ah[2][4], al[2][4], bh[4], bl[4];
#pragma unroll
        for (int mt = 0; mt < 2; ++mt) {
            uint32_t off = sw128((uint32_t)((m0 + mt * 16 + ar) * 128 + (ks * 16 + ak) * 2));
            ldm4(ah[mt], Ah + off);
            ldm4(al[mt], Al + off);
        }
        {
            uint32_t off = sw128((uint32_t)((n0w + bn) * 128 + (ks * 16 + bk) * 2));
            ldm4(bh, Bh + off);
            ldm4(bl, Bl + off);
        }
#pragma unroll
        for (int mt = 0; mt < 2; ++mt)
#pragma unroll
            for (int nt = 0; nt < 2; ++nt) {
                int o = nt << 1;
                mma16816(acc[mt][nt], ah[mt], bh[o], bh[o + 1]);
                mma16816(acc[mt][nt], ah[mt], bl[o], bl[o + 1]);
                mma16816(acc[mt][nt], al[mt], bh[o], bh[o + 1]);
            }
    }
}

// --------------------------- staging helpers -------------------------------
// A copy-stage (256 thr): rows p0..p0+127 from [p][ld] planes, cols koff..koff+63
__device__ __forceinline__ void stageA_planes(uint32_t Sa, const __nv_bfloat16* hi,
                                              const __nv_bfloat16* lo, int ld, int koff,
                                              int p0, int tid) {
    int row = tid >> 1, plane = tid & 1, p = p0 + row;
    const __nv_bfloat16* src = (plane ? lo : hi) + (size_t)(p < NPTS ? p : 0) * ld + koff;
    uint32_t zf = (p < NPTS) ? 16u : 0u;
    uint32_t base = Sa + (plane << 14);
#pragma unroll
    for (int j = 0; j < 8; ++j)
        cpasync16(base + sw128((uint32_t)(row * 128 + j * 16)), src + j * 8, zf);
}

// A gather-stage (512 thr): rows via nbr[:,kk], 64-col planes
__device__ __forceinline__ void stageA_gather512(uint32_t Sa, const __nv_bfloat16* hi,
                                                 const __nv_bfloat16* lo,
                                                 const int* __restrict__ nbr,
                                                 int p0, int kk, int tid) {
#pragma unroll
    for (int i = 0; i < 4; ++i) {
        int idx = tid + (i << 9);            // 0..2047
        int plane = idx >> 10, r10 = idx & 1023, row = r10 >> 3, j = r10 & 7;
        int p = p0 + row;
        int nb = (p < NPTS) ? __ldg(&nbr[(size_t)p * 27 + kk]) : -1;
        const __nv_bfloat16* src = (plane ? lo : hi) + (size_t)(nb < 0 ? 0 : nb) * 64 + j * 8;
        cpasync16(Sa + (plane << 14) + sw128((uint32_t)(row * 128 + j * 16)),
                  src, (nb >= 0) ? 16u : 0u);
    }
}

// B copy-stage, 256 thr: 64 rows x 64k from [n][srcld] planes at column koff
__device__ __forceinline__ void stageB_rows(uint32_t Sb, const __nv_bfloat16* hi,
                                            const __nv_bfloat16* lo, int srcld,
                                            int koff, int tid) {
#pragma unroll
    for (int j = 0; j < 4; ++j) {
        int fl = tid + (j << 8);
        int plane = fl >> 9, r9 = fl & 511, n = r9 >> 3, jj = r9 & 7;
        const __nv_bfloat16* src = (plane ? lo : hi) + (size_t)n * srcld + koff + jj * 8;
        cpasync16(Sb + (plane << 13) + sw128((uint32_t)(n * 128 + jj * 16)), src, 16u);
    }
}
// B copy-stage, 512 thr (srcld = 64)
__device__ __forceinline__ void stageB_rows512(uint32_t Sb, const __nv_bfloat16* hi,
                                               const __nv_bfloat16* lo, int tid) {
#pragma unroll
    for (int j = 0; j < 2; ++j) {
        int fl = tid + (j << 9);
        int plane = fl >> 9, r9 = fl & 511, n = r9 >> 3, jj = r9 & 7;
        const __nv_bfloat16* src = (plane ? lo : hi) + (size_t)n * 64 + jj * 8;
        cpasync16(Sb + (plane << 13) + sw128((uint32_t)(n * 128 + jj * 16)), src, 16u);
    }
}

// relu + split epilogue into [p][ld] planes (8-warp m32n32 variant)
__device__ __forceinline__ void epi_planes32(const float acc[2][4][4],
                                             __nv_bfloat16* ghi, __nv_bfloat16* glo,
                                             int ld, int colbase,
                                             int p0, int m0, int n0w, int lane) {
    int r0 = lane >> 2, c0 = (lane & 3) << 1;
#pragma unroll
    for (int mt = 0; mt < 2; ++mt)
#pragma unroll
        for (int nt = 0; nt < 4; ++nt)
#pragma unroll
            for (int h = 0; h < 2; ++h) {
                int p = p0 + m0 + mt * 16 + r0 + h * 8;
                if (p >= NPTS) continue;
                int col = colbase + n0w + nt * 8 + c0;
                float v0 = fmaxf(acc[mt][nt][h * 2 + 0], 0.f);
                float v1 = fmaxf(acc[mt][nt][h * 2 + 1], 0.f);
                uint32_t hv = packbf(v0, v1);
                uint32_t lv = packbf(v0 - lo2f(hv), v1 - hi2f(hv));
                *(uint32_t*)(ghi + (size_t)p * ld + col) = hv;
                *(uint32_t*)(glo + (size_t)p * ld + col) = lv;
            }
}

extern __shared__ char dsm[];

// ------------------------- weight prep (once per graph) --------------------
__global__ void prep_w(const float* __restrict__ W1s, const float* __restrict__ Wks,
                       const float* __restrict__ W2s, const float* __restrict__ Wf) {
    int idx = blockIdx.x * 256 + threadIdx.x;
    float w;
    __nv_bfloat16 *dh, *dl;
    size_t d;
    if (idx < 49152) {
        int i = idx / 8192, r = idx % 8192, n = r / 128, k = r % 128;
        w = W1s[(size_t)i * 8192 + (size_t)k * 64 + n];
        dh = w1t_hi; dl = w1t_lo; d = (size_t)i * 8192 + n * 128 + k;
    } else if (idx < 712704) {
        int t = idx - 49152;
        int j = t / 4096, r = t % 4096, n = r / 64, k = r % 64;
        w = Wks[(size_t)j * 4096 + (size_t)k * 64 + n];
        dh = wkt_hi; dl = wkt_lo; d = (size_t)j * 4096 + n * 64 + k;
    } else if (idx < 761856) {
        int t = idx - 712704;
        int i = t / 8192, r = t % 8192, n = r / 64, k = r % 64;
        w = W2s[(size_t)i * 8192 + (size_t)k * 128 + n];
        dh = w2t_hi; dl = w2t_lo; d = (size_t)i * 8192 + n * 64 + k;
    } else if (idx < 778240) {
        int t = idx - 761856;
        int n = t / 128, k = t % 128;
        w = Wf[(size_t)k * 128 + n];
        dh = wft_hi; dl = wft_lo; d = (size_t)n * 128 + k;
    } else return;
    __nv_bfloat16 h = __float2bfloat16(w);
    dh[d] = h;
    dl[d] = __float2bfloat16(w - __bfloat162float(h));
}

// x -> split planes (once per graph)
__global__ void prep_x(const float* __restrict__ x) {
    size_t i4 = (size_t)blockIdx.x * 256 + threadIdx.x;
    if (i4 >= (size_t)NPTS * 128 / 4) return;
    float4 v = ((const float4*)x)[i4];
    uint32_t h01 = packbf(v.x, v.y), h23 = packbf(v.z, v.w);
    uint32_t l01 = packbf(v.x - lo2f(h01), v.y - hi2f(h01));
    uint32_t l23 = packbf(v.z - lo2f(h23), v.w - hi2f(h23));
    ((uint32_t*)xp_hi)[i4 * 2] = h01; ((uint32_t*)xp_hi)[i4 * 2 + 1] = h23;
    ((uint32_t*)xp_lo)[i4 * 2] = l01; ((uint32_t*)xp_lo)[i4 * 2 + 1] = l23;
}

// --------------------------------- conv ------------------------------------
// u[branch] = relu( sum_kk gather(t[branch], nbr[:,kk]) @ Wk[layer,kk] )
// 512 threads, 16 warps of m32 x n16; double-buffered cp.async stages.
__global__ void __launch_bounds__(512)
conv_kernel(const int* __restrict__ nbr, int unit) {
    uint32_t sb = smem_u32(dsm);
    int tid = threadIdx.x, lane = tid & 31, wid = tid >> 5;
    int p0 = blockIdx.x * 128;
    int branch = blockIdx.y;
    int layer = unit + 3 * branch;
    int m0 = (wid & 3) * 32, n0w = (wid >> 2) * 16;
    const __nv_bfloat16* th = t_hi[branch];
    const __nv_bfloat16* tl = t_lo[branch];
    const __nv_bfloat16* wh = wkt_hi + (size_t)layer * 27 * 4096;
    const __nv_bfloat16* wl = wkt_lo + (size_t)layer * 27 * 4096;
    float acc[2][2][4] = {};

    // prologue: stage kk=0 into buffer 0
    stageA_gather512(sb, th, tl, nbr, p0, 0, tid);
    stageB_rows512(sb + 32768, wh, wl, tid);
    CP_COMMIT();

    for (int kk = 0; kk < 27; ++kk) {
        uint32_t S = sb + (uint32_t)(kk & 1) * 49152;
        if (kk < 26) {
            uint32_t S2 = sb + (uint32_t)((kk + 1) & 1) * 49152;
            stageA_gather512(S2, th, tl, nbr, p0, kk + 1, tid);
            stageB_rows512(S2 + 32768, wh + (size_t)(kk + 1) * 4096,
                           wl + (size_t)(kk + 1) * 4096, tid);
            CP_COMMIT();
            CP_WAIT(1);
        } else {
            CP_WAIT(0);
        }
        __syncthreads();
        mma_chunk16(acc, S, S + 16384, S + 32768, S + 40960, m0, n0w, lane);
        __syncthreads();
    }

    // relu + split epilogue into u planes
    int r0 = lane >> 2, c0 = (lane & 3) << 1;
    __nv_bfloat16* uh = u_hi[branch];
    __nv_bfloat16* ul = u_lo[branch];
#pragma unroll
    for (int mt = 0; mt < 2; ++mt)
#pragma unroll
        for (int nt = 0; nt < 2; ++nt)
#pragma unroll
            for (int h = 0; h < 2; ++h) {
                int p = p0 + m0 + mt * 16 + r0 + h * 8;
                if (p >= NPTS) continue;
                int col = n0w + nt * 8 + c0;
                float v0 = fmaxf(acc[mt][nt][h * 2 + 0], 0.f);
                float v1 = fmaxf(acc[mt][nt][h * 2 + 1], 0.f);
                uint32_t hv = packbf(v0, v1);
                uint32_t lv = packbf(v0 - lo2f(hv), v1 - hi2f(hv));
                *(uint32_t*)(uh + (size_t)p * 64 + col) = hv;
                *(uint32_t*)(ul + (size_t)p * 64 + col) = lv;
            }
}

// ------------------------------ fc1 ----------------------------------------
// t[branch] = relu( src @ W1[layer] ), K=128 (2 chunks), N=64; src = xp or ab[branch]
__global__ void __launch_bounds__(256)
fc1_kernel(int unit) {
    uint32_t sb = smem_u32(dsm);
    int tid = threadIdx.x, lane = tid & 31, wid = tid >> 5;
    int p0 = blockIdx.x * 128;
    int branch = blockIdx.y;
    int layer = unit + 3 * branch;
    int m0 = (wid & 3) * 32, n0w = (wid >> 2) * 32;
    const __nv_bfloat16* sh = (unit == 0) ? xp_hi : ab_hi[branch];
    const __nv_bfloat16* sl = (unit == 0) ? xp_lo : ab_lo[branch];
    const __nv_bfloat16* wh = w1t_hi + (size_t)layer * 8192;
    const __nv_bfloat16* wl = w1t_lo + (size_t)layer * 8192;
    float acc[2][4][4] = {};

#pragma unroll
    for (int ck = 0; ck < 2; ++ck) {
        stageA_planes(sb, sh, sl, 128, ck * 64, p0, tid);
        stageB_rows(sb + 32768, wh, wl, 128, ck * 64, tid);
        CP_COMMIT();
        CP_WAIT(0);
        __syncthreads();
        mma_chunk32(acc, sb, sb + 16384, sb + 32768, sb + 40960, m0, n0w, lane);
        __syncthreads();
    }
    epi_planes32(acc, t_hi[branch], t_lo[branch], 64, 0, p0, m0, n0w, lane);
}

// ------------------------------ fc2 ----------------------------------------
// ab[branch] = relu( u[branch] @ W2[layer] + res ), N=128 via blockIdx.y halves
__global__ void __launch_bounds__(256)
fc2_kernel(int unit) {
    uint32_t sb = smem_u32(dsm);
    int tid = threadIdx.x, lane = tid & 31, wid = tid >> 5;
    int p0 = blockIdx.x * 128, cb = blockIdx.y * 64;
    int branch = blockIdx.z;
    int layer = unit + 3 * branch;
    int m0 = (wid & 3) * 32, n0w = (wid >> 2) * 32;
    const __nv_bfloat16* rh = (unit == 0) ? xp_hi : ab_hi[branch];
    const __nv_bfloat16* rl = (unit == 0) ? xp_lo : ab_lo[branch];
    const __nv_bfloat16* wh = w2t_hi + (size_t)layer * 8192 + (size_t)cb * 64;
    const __nv_bfloat16* wl = w2t_lo + (size_t)layer * 8192 + (size_t)cb * 64;
    float acc[2][4][4] = {};

    stageA_planes(sb, u_hi[branch], u_lo[branch], 64, 0, p0, tid);
    stageB_rows(sb + 32768, wh, wl, 64, 0, tid);
    CP_COMMIT();
    CP_WAIT(0);
    __syncthreads();
    mma_chunk32(acc, sb, sb + 16384, sb + 32768, sb + 40960, m0, n0w, lane);

    __nv_bfloat16* oh = ab_hi[branch];
    __nv_bfloat16* ol = ab_lo[branch];
    int r0 = lane >> 2, c0 = (lane & 3) << 1;
#pragma unroll
    for (int mt = 0; mt < 2; ++mt)
#pragma unroll
        for (int nt = 0; nt < 4; ++nt)
#pragma unroll
            for (int h = 0; h < 2; ++h) {
                int p = p0 + m0 + mt * 16 + r0 + h * 8;
                if (p >= NPTS) continue;
                int col = cb + n0w + nt * 8 + c0;
                uint32_t rhv = *(const uint32_t*)(rh + (size_t)p * 128 + col);
                uint32_t rlv = *(const uint32_t*)(rl + (size_t)p * 128 + col);
                float v0 = fmaxf(acc[mt][nt][h * 2 + 0] + lo2f(rhv) + lo2f(rlv), 0.f);
                float v1 = fmaxf(acc[mt][nt][h * 2 + 1] + hi2f(rhv) + hi2f(rlv), 0.f);
                uint32_t hv = packbf(v0, v1);
                uint32_t lv = packbf(v0 - lo2f(hv), v1 - hi2f(hv));
                *(uint32_t*)(oh + (size_t)p * 128 + col) = hv;
                *(uint32_t*)(ol + (size_t)p * 128 + col) = lv;
            }
}

// ------------------------------ final --------------------------------------
// out = a * sigmoid(b @ Wf) + x,  K=128 (2 chunks), N=128 via blockIdx.y
__global__ void __launch_bounds__(256)
final_kernel(const float* __restrict__ x, float* __restrict__ out) {
    uint32_t sb = smem_u32(dsm);
    int tid = threadIdx.x, lane = tid & 31, wid = tid >> 5;
    int p0 = blockIdx.x * 128, cb = blockIdx.y * 64;
    int m0 = (wid & 3) * 32, n0w = (wid >> 2) * 32;
    const __nv_bfloat16* wh = wft_hi + (size_t)cb * 128;
    const __nv_bfloat16* wl = wft_lo + (size_t)cb * 128;
    float acc[2][4][4] = {};

#pragma unroll
    for (int ck = 0; ck < 2; ++ck) {
        stageA_planes(sb, ab_hi[1], ab_lo[1], 128, ck * 64, p0, tid);
        stageB_rows(sb + 32768, wh, wl, 128, ck * 64, tid);
        CP_COMMIT();
        CP_WAIT(0);
        __syncthreads();
        mma_chunk32(acc, sb, sb + 16384, sb + 32768, sb + 40960, m0, n0w, lane);
        __syncthreads();
    }

    int r0 = lane >> 2, c0 = (lane & 3) << 1;
#pragma unroll
    for (int mt = 0; mt < 2; ++mt)
#pragma unroll
        for (int nt = 0; nt < 4; ++nt)
#pragma unroll
            for (int h = 0; h < 2; ++h) {
                int p = p0 + m0 + mt * 16 + r0 + h * 8;
                if (p >= NPTS) continue;
                int col = cb + n0w + nt * 8 + c0;
                uint32_t ahv = *(const uint32_t*)(ab_hi[0] + (size_t)p * 128 + col);
                uint32_t alv = *(const uint32_t*)(ab_lo[0] + (size_t)p * 128 + col);
                float a0 = lo2f(ahv) + lo2f(alv), a1 = hi2f(ahv) + hi2f(alv);
                float2 xv = *(const float2*)(x + (size_t)p * 128 + col);
                float g0 = acc[mt][nt][h * 2 + 0], g1 = acc[mt][nt][h * 2 + 1];
                float2 v;
                v.x = a0 * (1.f / (1.f + __expf(-g0))) + xv.x;
                v.y = a1 * (1.f / (1.f + __expf(-g1))) + xv.y;
                *(float2*)(out + (size_t)p * 128 + col) = v;
            }
}

// ---------------------------------------------------------------------------
extern "C" void kernel_launch(void* const* d_in, const int* in_sizes, int n_in,
                              void* d_out, int out_size) {
    const float* x   = (const float*)d_in[0];
    const float* W1s = (const float*)d_in[1];
    const float* Wks = (const float*)d_in[2];
    const float* W2s = (const float*)d_in[3];
    const float* Wf  = (const float*)d_in[4];
    const int*   nbr = (const int*)d_in[5];
    float*       out = (float*)d_out;

    cudaFuncSetAttribute(conv_kernel,  cudaFuncAttributeMaxDynamicSharedMemorySize, 98304);
    cudaFuncSetAttribute(fc1_kernel,   cudaFuncAttributeMaxDynamicSharedMemorySize, 49152);
    cudaFuncSetAttribute(fc2_kernel,   cudaFuncAttributeMaxDynamicSharedMemorySize, 49152);
    cudaFuncSetAttribute(final_kernel, cudaFuncAttributeMaxDynamicSharedMemorySize, 49152);

    prep_w<<<3040, 256>>>(W1s, Wks, W2s, Wf);
    prep_x<<<(NPTS * 128 / 4 + 255) / 256, 256>>>(x);

    dim3 blk256(256), blk512(512);
    dim3 gfc1(NBLK, 2), gconv(NBLK, 2), gfc2(NBLK, 2, 2), gfin(NBLK, 2);

    for (int i = 0; i < 3; ++i) {
        fc1_kernel<<<gfc1, blk256, 49152>>>(i);
        conv_kernel<<<gconv, blk512, 98304>>>(nbr, i);
        fc2_kernel<<<gfc2, blk256, 49152>>>(i);
    }
    final_kernel<<<gfin, blk256, 49152>>>(x, out);
}